// round 4
// baseline (speedup 1.0000x reference)
#include <cuda_runtime.h>
#include <math.h>

#define BATCH 8
#define NVERT 8192
#define NPD 64
#define NSAMP (NPD*NPD)      // 4096
#define CH 32                // chunks (blocks) per batch
#define JCHUNK (NVERT/CH)    // 256 vertices per block
#define JT 16                // j's per stage (double-buffered)
#define NSTAGE (JCHUNK/JT)   // 16
#define NTHR 256

// ---- device scratch (no allocations allowed) ----
__device__ float4   g_stats[BATCH*CH];          // per-chunk (sx,sxx,sy,syy)
__device__ float    g_partial[BATCH*CH*NSAMP];  // 4 MB partial GEMM results
__device__ float    g_K[BATCH*NSAMP];           // reduced, coeff-scaled
__device__ float    g_ssum[BATCH*CH];           // per-segment sums
__device__ unsigned g_cntA[BATCH];
__device__ unsigned g_cntB[BATCH];
__device__ unsigned g_cntC[BATCH];

__device__ __forceinline__ float ex2f(float x) {
    float y;
    asm("ex2.approx.ftz.f32 %0, %1;" : "=f"(y) : "f"(x));
    return y;
}

// Packed 2xFP32 FMA (Blackwell FFMA2, PTX-only)
__device__ __forceinline__ unsigned long long ffma2(
    unsigned long long a, unsigned long long b, unsigned long long c)
{
    unsigned long long d;
    asm("fma.rn.f32x2 %0, %1, %2, %3;" : "=l"(d) : "l"(a), "l"(b), "l"(c));
    return d;
}

__device__ __forceinline__ void spin_until(volatile unsigned* p, unsigned v) {
    while (*p < v) { }
}

// ==================== single fused persistent kernel ====================
// grid = 256 blocks (batch = blk>>5, chunk = blk&31), 256 threads.
// 2 blocks/SM co-resident (capacity 296 >= 256); 16 warps/SM.
__global__ void __launch_bounds__(NTHR, 2) k_fused(const float* __restrict__ T,
                                                   const float* __restrict__ S,
                                                   float* __restrict__ out)
{
    __shared__ __align__(16) float2 sExd[2][JT][NPD];   // duplicated (ex,ex), 16 KB
    __shared__ __align__(16) float  sEy[2][JT][NPD];    // 8 KB
    __shared__ __align__(16) float2 sT[JCHUNK];         // 2 KB
    __shared__ __align__(16) float4 s4[NTHR];           // 4 KB (phase-C staging)
    __shared__ float  sG[NPD];
    __shared__ float4 sW[8];
    __shared__ float  sKx, sCoeff, sInv;
    __shared__ int    sIsLast;

    const int tid = threadIdx.x;
    const int bb  = blockIdx.x >> 5;
    const int ch  = blockIdx.x & 31;

    // ---- stage T chunk + grid into shared ----
    ((float2*)sT)[tid] = ((const float2*)(T + (bb * NVERT + ch * JCHUNK) * 2))[tid];
    if (tid < NPD) sG[tid] = S[tid * 2 + 1];   // S[0,c,1] = g[c] exactly
    __syncthreads();

    // ================= Phase A: chunk stats + sigma barrier =================
    {
        float2 v0 = sT[tid];                   // one vertex per thread
        float sx  = v0.x;
        float sy  = v0.y;
        float sxx = v0.x * v0.x;
        float syy = v0.y * v0.y;
        #pragma unroll
        for (int o = 16; o; o >>= 1) {
            sx  += __shfl_xor_sync(~0u, sx,  o);
            sxx += __shfl_xor_sync(~0u, sxx, o);
            sy  += __shfl_xor_sync(~0u, sy,  o);
            syy += __shfl_xor_sync(~0u, syy, o);
        }
        if ((tid & 31) == 0) sW[tid >> 5] = make_float4(sx, sxx, sy, syy);
        __syncthreads();
        if (tid == 0) {
            float4 r = sW[0];
            #pragma unroll
            for (int w = 1; w < 8; ++w) {
                r.x += sW[w].x; r.y += sW[w].y; r.z += sW[w].z; r.w += sW[w].w;
            }
            g_stats[blockIdx.x] = r;
            __threadfence();
            atomicAdd(&g_cntA[bb], 1u);
            spin_until(&g_cntA[bb], CH);
            __threadfence();
        }
        __syncthreads();
    }

    // Every block deterministically combines the 32 chunk partials -> sigma.
    if (tid < 32) {
        float4 st = __ldcg(&g_stats[bb * 32 + tid]);
        float sx = st.x, sxx = st.y, sy = st.z, syy = st.w;
        #pragma unroll
        for (int o = 16; o; o >>= 1) {
            sx  += __shfl_xor_sync(~0u, sx,  o);
            sxx += __shfl_xor_sync(~0u, sxx, o);
            sy  += __shfl_xor_sync(~0u, sy,  o);
            syy += __shfl_xor_sync(~0u, syy, o);
        }
        if (tid == 0) {
            const double n = (double)NVERT;
            double vx = ((double)sxx - (double)sx * (double)sx / n) / (n - 1.0);
            double vy = ((double)syy - (double)sy * (double)sy / n) / (n - 1.0);
            if (vx < 0.0) vx = 0.0;
            if (vy < 0.0) vy = 0.0;
            double sigma = 0.5 * (sqrt(vx) + sqrt(vy));
            const double bd = 1.0 / 63.0;            // (U-L)/(NPD-1)
            if (sigma < bd) sigma = bd;
            // D=2: C = NV^{-1/6};  CN = -2^{13/3}/2;  CF = 2^{13/3}/(2*pi)
            const double p   = exp2(13.0 / 3.0);
            const double s2  = sigma * sigma;
            sKx    = (float)((-0.5 * p) / s2 * 1.4426950408889634);
            sCoeff = (float)((p / (2.0 * M_PI)) / s2 / (double)NVERT);
        }
    }
    __syncthreads();
    const float kx = sKx;

    // ================= Phase B: separable-KDE GEMM (pipelined) =================
    // Thread tile: 4(a) x 4(b'). 16x16 thread grid covers 64x64.
    unsigned long long acc[4][2];
    #pragma unroll
    for (int i = 0; i < 4; ++i) { acc[i][0] = 0ull; acc[i][1] = 0ull; }

    const int ta = tid >> 4;          // 0..15 -> a rows [ta*4, ta*4+4)
    const int tb = tid & 15;          // 0..15 -> b' cols [tb*4, tb*4+4)
    const int av = tid & 63;          // fill-stage grid index
    const int jbase = tid >> 6;       // 0..3
    const float ga = sG[av];

    // Prologue: fill stage 0 (each thread: 4 j's x 1 grid point)
    #pragma unroll
    for (int it = 0; it < 4; ++it) {
        int jj = it * 4 + jbase;
        float2 t = sT[jj];
        float dx = ga - t.x;
        float dy = ga - t.y;
        float ex = ex2f(kx * (dx * dx));
        float ey = ex2f(kx * (dy * dy));
        sExd[0][jj][av] = make_float2(ex, ex);
        sEy[0][jj][av]  = ey;
    }
    __syncthreads();

    for (int s = 0; s < NSTAGE; ++s) {
        const int cur = s & 1;
        if (s + 1 < NSTAGE) {
            const int nxt = cur ^ 1;
            #pragma unroll
            for (int it = 0; it < 4; ++it) {
                int jj = it * 4 + jbase;
                float2 t = sT[(s + 1) * JT + jj];
                float dx = ga - t.x;
                float dy = ga - t.y;
                float ex = ex2f(kx * (dx * dx));
                float ey = ex2f(kx * (dy * dy));
                sExd[nxt][jj][av] = make_float2(ex, ex);
                sEy[nxt][jj][av]  = ey;
            }
        }
        #pragma unroll
        for (int jj = 0; jj < JT; ++jj) {
            ulonglong2 ax01 = *(const ulonglong2*)&sExd[cur][jj][ta * 4];      // (a0,a0),(a1,a1)
            ulonglong2 ax23 = *(const ulonglong2*)&sExd[cur][jj][ta * 4 + 2];  // (a2,a2),(a3,a3)
            ulonglong2 bv   = *(const ulonglong2*)&sEy[cur][jj][tb * 4];       // (b0,b1),(b2,b3)
            acc[0][0] = ffma2(ax01.x, bv.x, acc[0][0]);
            acc[0][1] = ffma2(ax01.x, bv.y, acc[0][1]);
            acc[1][0] = ffma2(ax01.y, bv.x, acc[1][0]);
            acc[1][1] = ffma2(ax01.y, bv.y, acc[1][1]);
            acc[2][0] = ffma2(ax23.x, bv.x, acc[2][0]);
            acc[2][1] = ffma2(ax23.x, bv.y, acc[2][1]);
            acc[3][0] = ffma2(ax23.y, bv.x, acc[3][0]);
            acc[3][1] = ffma2(ax23.y, bv.y, acc[3][1]);
        }
        __syncthreads();
    }

    // write partials
    {
        float* outp = g_partial + blockIdx.x * NSAMP;
        #pragma unroll
        for (int i = 0; i < 4; ++i) {
            ulonglong2 v; v.x = acc[i][0]; v.y = acc[i][1];
            *(ulonglong2*)(outp + (ta * 4 + i) * NPD + tb * 4) = v;
        }
    }
    __threadfence();
    __syncthreads();
    if (tid == 0) {
        atomicAdd(&g_cntB[bb], 1u);
        spin_until(&g_cntB[bb], CH);
        __threadfence();
    }
    __syncthreads();

    // ================= Phase C: cooperative reduce + segment sums =================
    // Block (bb,ch) reduces image float4 positions [ch*32, ch*32+32).
    {
        const int p4 = ch * 32 + (tid & 31);
        const int q  = tid >> 5;                       // 0..7
        const float4* base = (const float4*)g_partial + (size_t)bb * 32 * 1024 + p4;
        float4 s = make_float4(0.f, 0.f, 0.f, 0.f);
        #pragma unroll
        for (int c = 0; c < 4; ++c) {
            float4 v = __ldcg(base + (size_t)(q * 4 + c) * 1024);
            s.x += v.x; s.y += v.y; s.z += v.z; s.w += v.w;
        }
        s4[tid] = s;
        __syncthreads();
        if (tid < 32) {
            float4 r = s4[tid];
            #pragma unroll
            for (int k = 1; k < 8; ++k) {
                float4 v = s4[tid + k * 32];
                r.x += v.x; r.y += v.y; r.z += v.z; r.w += v.w;
            }
            const float cf = sCoeff;
            r.x *= cf; r.y *= cf; r.z *= cf; r.w *= cf;
            ((float4*)g_K)[bb * 1024 + ch * 32 + tid] = r;
            float ls = r.x + r.y + r.z + r.w;
            #pragma unroll
            for (int o = 16; o; o >>= 1) ls += __shfl_xor_sync(~0u, ls, o);
            if (tid == 0) g_ssum[bb * 32 + ch] = ls;
        }
        __syncthreads();
    }
    if (tid == 0) {
        __threadfence();
        unsigned old = atomicAdd(&g_cntC[bb], 1u);
        sIsLast = (old == CH - 1) ? 1 : 0;
    }
    __syncthreads();
    if (!sIsLast) return;

    // ================= Finalize (one block per batch) =================
    __threadfence();
    if (tid < 32) {
        float v = __ldcg(&g_ssum[bb * 32 + tid]);
        #pragma unroll
        for (int o = 16; o; o >>= 1) v += __shfl_xor_sync(~0u, v, o);
        if (tid == 0) sInv = 1.0f / fmaxf(v, 1e-5f);
    }
    __syncthreads();
    const float inv = sInv;
    const float4* kp = (const float4*)g_K + bb * 1024;
    float4* op = (float4*)out + bb * 1024;
    #pragma unroll
    for (int k = 0; k < 4; ++k) {
        float4 v = __ldcg(kp + tid + k * NTHR);
        v.x *= inv; v.y *= inv; v.z *= inv; v.w *= inv;
        op[tid + k * NTHR] = v;
    }
    if (tid == 0) {   // reset barrier counters for the next graph replay
        g_cntA[bb] = 0u; g_cntB[bb] = 0u; g_cntC[bb] = 0u;
    }
}

extern "C" void kernel_launch(void* const* d_in, const int* in_sizes, int n_in,
                              void* d_out, int out_size)
{
    const float* T = (const float*)d_in[0];
    const float* S = (const float*)d_in[1];
    if (n_in >= 2 && in_sizes[0] == BATCH * NSAMP * 2 &&
        in_sizes[1] == BATCH * NVERT * 2) {
        T = (const float*)d_in[1];
        S = (const float*)d_in[0];
    }
    k_fused<<<BATCH * CH, NTHR>>>(T, S, (float*)d_out);
}

// round 5
// speedup vs baseline: 1.0789x; 1.0789x over previous
#include <cuda_runtime.h>
#include <math.h>

#define BATCH 8
#define NVERT 8192
#define NPD 64
#define NSAMP (NPD*NPD)      // 4096
#define CH 64                // chunks (blocks) per batch
#define JCHUNK (NVERT/CH)    // 128 vertices per block
#define JT 16                // j's per stage (double-buffered)
#define NSTAGE (JCHUNK/JT)   // 8
#define NTHR 128

// ---- device scratch (no allocations allowed) ----
__device__ float4   g_stats[BATCH*CH];
__device__ float    g_partial[BATCH*CH*NSAMP];  // 8 MB partial GEMM results
__device__ float    g_K[BATCH*NSAMP];
__device__ float    g_ssum[BATCH*CH];
__device__ unsigned g_cntA[BATCH];
__device__ unsigned g_cntB[BATCH];
__device__ unsigned g_cntC[BATCH];

__device__ __forceinline__ float ex2f(float x) {
    float y;
    asm("ex2.approx.ftz.f32 %0, %1;" : "=f"(y) : "f"(x));
    return y;
}

// Packed 2xFP32 FMA (Blackwell FFMA2, PTX-only)
__device__ __forceinline__ unsigned long long ffma2(
    unsigned long long a, unsigned long long b, unsigned long long c)
{
    unsigned long long d;
    asm("fma.rn.f32x2 %0, %1, %2, %3;" : "=l"(d) : "l"(a), "l"(b), "l"(c));
    return d;
}

__device__ __forceinline__ void spin_until(volatile unsigned* p, unsigned v) {
    while (*p < v) { }
}

// ==================== single fused persistent kernel ====================
// grid = 512 blocks (batch = blk>>6, chunk = blk&63), 128 threads.
// 3-4 blocks/SM co-resident (capacity 592 >= 512) -> 6-8 warps/SMSP.
__global__ void __launch_bounds__(NTHR, 4) k_fused(const float* __restrict__ T,
                                                   const float* __restrict__ S,
                                                   float* __restrict__ out)
{
    __shared__ __align__(16) float2 sExd[2][JT][NPD];   // duplicated (ex,ex), 16 KB
    __shared__ __align__(16) float  sEy[2][JT][NPD];    // 8 KB
    __shared__ __align__(16) float2 sT[JCHUNK];         // 1 KB
    __shared__ __align__(16) float4 s4[NTHR];           // 2 KB (phase-C staging)
    __shared__ float  sG[NPD];
    __shared__ float4 sW[4];
    __shared__ float  sKx, sCoeff, sInv;
    __shared__ int    sIsLast;

    const int tid = threadIdx.x;
    const int bb  = blockIdx.x >> 6;
    const int ch  = blockIdx.x & 63;

    // ---- stage T chunk + grid into shared ----
    ((float2*)sT)[tid] = ((const float2*)(T + (bb * NVERT + ch * JCHUNK) * 2))[tid];
    if (tid < NPD) sG[tid] = S[tid * 2 + 1];   // S[0,c,1] = g[c] exactly
    __syncthreads();

    // ================= Phase A: chunk stats + sigma barrier =================
    {
        float2 v0 = sT[tid];                   // one vertex per thread
        float sx  = v0.x;
        float sy  = v0.y;
        float sxx = v0.x * v0.x;
        float syy = v0.y * v0.y;
        #pragma unroll
        for (int o = 16; o; o >>= 1) {
            sx  += __shfl_xor_sync(~0u, sx,  o);
            sxx += __shfl_xor_sync(~0u, sxx, o);
            sy  += __shfl_xor_sync(~0u, sy,  o);
            syy += __shfl_xor_sync(~0u, syy, o);
        }
        if ((tid & 31) == 0) sW[tid >> 5] = make_float4(sx, sxx, sy, syy);
        __syncthreads();
        if (tid == 0) {
            float4 r = sW[0];
            #pragma unroll
            for (int w = 1; w < 4; ++w) {
                r.x += sW[w].x; r.y += sW[w].y; r.z += sW[w].z; r.w += sW[w].w;
            }
            g_stats[blockIdx.x] = r;
            __threadfence();
            atomicAdd(&g_cntA[bb], 1u);
            spin_until(&g_cntA[bb], CH);
            __threadfence();
        }
        __syncthreads();
    }

    // Every block deterministically combines the 64 chunk partials -> sigma.
    if (tid < 32) {
        float4 sa = __ldcg(&g_stats[bb * 64 + tid]);
        float4 sb = __ldcg(&g_stats[bb * 64 + 32 + tid]);
        float sx = sa.x + sb.x, sxx = sa.y + sb.y;
        float sy = sa.z + sb.z, syy = sa.w + sb.w;
        #pragma unroll
        for (int o = 16; o; o >>= 1) {
            sx  += __shfl_xor_sync(~0u, sx,  o);
            sxx += __shfl_xor_sync(~0u, sxx, o);
            sy  += __shfl_xor_sync(~0u, sy,  o);
            syy += __shfl_xor_sync(~0u, syy, o);
        }
        if (tid == 0) {
            const double n = (double)NVERT;
            double vx = ((double)sxx - (double)sx * (double)sx / n) / (n - 1.0);
            double vy = ((double)syy - (double)sy * (double)sy / n) / (n - 1.0);
            if (vx < 0.0) vx = 0.0;
            if (vy < 0.0) vy = 0.0;
            double sigma = 0.5 * (sqrt(vx) + sqrt(vy));
            const double bd = 1.0 / 63.0;            // (U-L)/(NPD-1)
            if (sigma < bd) sigma = bd;
            // D=2: C = NV^{-1/6};  CN = -2^{13/3}/2;  CF = 2^{13/3}/(2*pi)
            const double p   = exp2(13.0 / 3.0);
            const double s2  = sigma * sigma;
            sKx    = (float)((-0.5 * p) / s2 * 1.4426950408889634);
            sCoeff = (float)((p / (2.0 * M_PI)) / s2 / (double)NVERT);
        }
    }
    __syncthreads();
    const float kx = sKx;

    // ================= Phase B: separable-KDE GEMM (pipelined) =================
    // Thread tile: 8(a) x 4(b'). 8x16 thread grid covers 64x64.
    unsigned long long acc[8][2];
    #pragma unroll
    for (int i = 0; i < 8; ++i) { acc[i][0] = 0ull; acc[i][1] = 0ull; }

    const int ta = tid >> 4;          // 0..7  -> a rows [ta*8, ta*8+8)
    const int tb = tid & 15;          // 0..15 -> b' cols [tb*4, tb*4+4)
    const int av = tid & 63;          // fill-stage grid index
    const int jbase = tid >> 6;       // 0/1
    const float ga = sG[av];

    // Prologue: fill stage 0 (each thread: 8 j's x 1 grid point)
    #pragma unroll
    for (int it = 0; it < 8; ++it) {
        int jj = it * 2 + jbase;
        float2 t = sT[jj];
        float dx = ga - t.x;
        float dy = ga - t.y;
        float ex = ex2f(kx * (dx * dx));
        float ey = ex2f(kx * (dy * dy));
        sExd[0][jj][av] = make_float2(ex, ex);
        sEy[0][jj][av]  = ey;
    }
    __syncthreads();

    for (int s = 0; s < NSTAGE; ++s) {
        const int cur = s & 1;
        if (s + 1 < NSTAGE) {
            const int nxt = cur ^ 1;
            #pragma unroll
            for (int it = 0; it < 8; ++it) {
                int jj = it * 2 + jbase;
                float2 t = sT[(s + 1) * JT + jj];
                float dx = ga - t.x;
                float dy = ga - t.y;
                float ex = ex2f(kx * (dx * dx));
                float ey = ex2f(kx * (dy * dy));
                sExd[nxt][jj][av] = make_float2(ex, ex);
                sEy[nxt][jj][av]  = ey;
            }
        }
        #pragma unroll
        for (int jj = 0; jj < JT; ++jj) {
            const ulonglong2* axp = (const ulonglong2*)&sExd[cur][jj][ta * 8];
            ulonglong2 bv = *(const ulonglong2*)&sEy[cur][jj][tb * 4];
            #pragma unroll
            for (int i = 0; i < 4; ++i) {
                ulonglong2 ax = axp[i];
                acc[2*i  ][0] = ffma2(ax.x, bv.x, acc[2*i  ][0]);
                acc[2*i  ][1] = ffma2(ax.x, bv.y, acc[2*i  ][1]);
                acc[2*i+1][0] = ffma2(ax.y, bv.x, acc[2*i+1][0]);
                acc[2*i+1][1] = ffma2(ax.y, bv.y, acc[2*i+1][1]);
            }
        }
        __syncthreads();
    }

    // write partials
    {
        float* outp = g_partial + blockIdx.x * NSAMP;
        #pragma unroll
        for (int i = 0; i < 8; ++i) {
            ulonglong2 v; v.x = acc[i][0]; v.y = acc[i][1];
            *(ulonglong2*)(outp + (ta * 8 + i) * NPD + tb * 4) = v;
        }
    }
    __threadfence();
    __syncthreads();
    if (tid == 0) {
        atomicAdd(&g_cntB[bb], 1u);
        spin_until(&g_cntB[bb], CH);
        __threadfence();
    }
    __syncthreads();

    // ================= Phase C: cooperative reduce + segment sums =================
    // Block (bb,ch) reduces image float4 positions [ch*16, ch*16+16) over 64 chunks.
    {
        const int p4 = ch * 16 + (tid & 15);
        const int q  = tid >> 4;                       // 0..7
        const float4* base = (const float4*)g_partial + (size_t)bb * 64 * 1024 + p4;
        float4 s = make_float4(0.f, 0.f, 0.f, 0.f);
        #pragma unroll
        for (int c = 0; c < 8; ++c) {
            float4 v = __ldcg(base + (size_t)(q * 8 + c) * 1024);
            s.x += v.x; s.y += v.y; s.z += v.z; s.w += v.w;
        }
        s4[tid] = s;
        __syncthreads();
        if (tid < 16) {
            float4 r = s4[tid];
            #pragma unroll
            for (int k = 1; k < 8; ++k) {
                float4 v = s4[tid + k * 16];
                r.x += v.x; r.y += v.y; r.z += v.z; r.w += v.w;
            }
            const float cf = sCoeff;
            r.x *= cf; r.y *= cf; r.z *= cf; r.w *= cf;
            ((float4*)g_K)[bb * 1024 + ch * 16 + tid] = r;
            float ls = r.x + r.y + r.z + r.w;
            #pragma unroll
            for (int o = 8; o; o >>= 1) ls += __shfl_xor_sync(0xFFFFu, ls, o);
            if (tid == 0) g_ssum[bb * 64 + ch] = ls;
        }
        __syncthreads();
    }
    if (tid == 0) {
        __threadfence();
        unsigned old = atomicAdd(&g_cntC[bb], 1u);
        sIsLast = (old == CH - 1) ? 1 : 0;
    }
    __syncthreads();
    if (!sIsLast) return;

    // ================= Finalize (one block per batch) =================
    __threadfence();
    if (tid < 32) {
        float v = __ldcg(&g_ssum[bb * 64 + tid]) + __ldcg(&g_ssum[bb * 64 + 32 + tid]);
        #pragma unroll
        for (int o = 16; o; o >>= 1) v += __shfl_xor_sync(~0u, v, o);
        if (tid == 0) sInv = 1.0f / fmaxf(v, 1e-5f);
    }
    __syncthreads();
    const float inv = sInv;
    const float4* kp = (const float4*)g_K + bb * 1024;
    float4* op = (float4*)out + bb * 1024;
    #pragma unroll
    for (int k = 0; k < 8; ++k) {
        float4 v = __ldcg(kp + tid + k * NTHR);
        v.x *= inv; v.y *= inv; v.z *= inv; v.w *= inv;
        op[tid + k * NTHR] = v;
    }
    if (tid == 0) {   // reset barrier counters for the next graph replay
        g_cntA[bb] = 0u; g_cntB[bb] = 0u; g_cntC[bb] = 0u;
    }
}

extern "C" void kernel_launch(void* const* d_in, const int* in_sizes, int n_in,
                              void* d_out, int out_size)
{
    const float* T = (const float*)d_in[0];
    const float* S = (const float*)d_in[1];
    if (n_in >= 2 && in_sizes[0] == BATCH * NSAMP * 2 &&
        in_sizes[1] == BATCH * NVERT * 2) {
        T = (const float*)d_in[1];
        S = (const float*)d_in[0];
    }
    k_fused<<<BATCH * CH, NTHR>>>(T, S, (float*)d_out);
}